// round 15
// baseline (speedup 1.0000x reference)
#include <cuda_runtime.h>
#include <cuda_fp16.h>

typedef unsigned int u32;
typedef unsigned long long u64;

#define BT 128
#define XROWB 80                 // x rows: 5 nodes x 8 halves = 80B, uint4-aligned
// fp32 scalar region (float indices)
#define SF_WR 0                  // 5 x 24 (zero-padded)
#define SF_BM 120                // 24
#define SF_BU 144                // 24
#define SF_BF 168                // 24
#define SF_BR 192
// fp16 B matrices (byte offsets)
#define WFB_OFF 800              // [8][24]  layer1 (rows 6-7 zero)
#define WM1_OFF 1184             // [32][24] (rows 18-31 zero)
#define WM2_OFF (WM1_OFF + 1536)
#define WUH_OFF (WM2_OFF + 1536)
#define WUM_OFF (WUH_OFF + 1536)
#define X_OFF   7328             // fp16 x rows, BT x 80B
#define SMEM_BYTES (X_OFF + BT*XROWB)   // 17568 -> reg-capped 4 CTAs/SM

static __device__ __forceinline__ float tanhap(float x){
    float r; asm("tanh.approx.f32 %0, %1;" : "=f"(r) : "f"(x)); return r;
}
static __device__ __forceinline__ void ldm2(u32 addr, u32 a[2]){
    asm volatile("ldmatrix.sync.aligned.m8n8.x2.shared.b16 {%0,%1}, [%2];"
        : "=r"(a[0]),"=r"(a[1]) : "r"(addr));
}
static __device__ __forceinline__ void mmas(float d[4], const u32 a[4], const u32 b[2]){
    asm volatile("mma.sync.aligned.m16n8k16.row.col.f32.f16.f16.f32 "
        "{%0,%1,%2,%3}, {%4,%5,%6,%7}, {%8,%9}, {%0,%1,%2,%3};"
        : "+f"(d[0]),"+f"(d[1]),"+f"(d[2]),"+f"(d[3])
        : "r"(a[0]),"r"(a[1]),"r"(a[2]),"r"(a[3]), "r"(b[0]),"r"(b[1]));
}
static __device__ __forceinline__ void mmas8(float d[4], const u32 a[2], u32 b){
    asm volatile("mma.sync.aligned.m16n8k8.row.col.f32.f16.f16.f32 "
        "{%0,%1,%2,%3}, {%4,%5}, {%6}, {%0,%1,%2,%3};"
        : "+f"(d[0]),"+f"(d[1]),"+f"(d[2]),"+f"(d[3])
        : "r"(a[0]),"r"(a[1]), "r"(b));
}
static __device__ __forceinline__ u32 pkh2(float a, float b){
    __half2 h = __floats2half2_rn(a, b);
    return *(u32*)&h;
}
// k16 B fragment (.col) over k rows 0-15
static __device__ __forceinline__ void ldbfrag16(const __half* W, int nf, int lane, u32 r[2]){
    int k0 = (lane & 3)*2;
    int nn = nf*8 + (lane >> 2);
    u32 a = __half_as_ushort(W[k0*24 + nn]);
    u32 b = __half_as_ushort(W[(k0+1)*24 + nn]);
    u32 c = __half_as_ushort(W[(k0+8)*24 + nn]);
    u32 d = __half_as_ushort(W[(k0+9)*24 + nn]);
    r[0] = a | (b << 16);
    r[1] = c | (d << 16);
}
// k8 B fragment over k rows kbase..kbase+7
static __device__ __forceinline__ u32 ldbfrag8(const __half* W, int kbase, int nf, int lane){
    int k0 = kbase + (lane & 3)*2;
    int nn = nf*8 + (lane >> 2);
    return (u32)__half_as_ushort(W[k0*24 + nn])
         | ((u32)__half_as_ushort(W[(k0+1)*24 + nn]) << 16);
}

__global__ void __launch_bounds__(BT, 4) mp_kernel(
    const float* __restrict__ x,
    const float* __restrict__ Wf, const float* __restrict__ bf,
    const float* __restrict__ Wm, const float* __restrict__ bm,
    const float* __restrict__ Wu, const float* __restrict__ bu,
    const float* __restrict__ Wr, const float* __restrict__ br,
    float* __restrict__ out, int n)
{
    extern __shared__ __align__(16) char smc[];
    float* sf = (float*)smc;
    const int t = threadIdx.x;

    // ---- fp32 scalars (zero-padded to 24 cols) ----
    for (int k = t; k < 120; k += BT){ int r=k/24, c=k%24; sf[SF_WR+k] = (c<18)? Wr[r*18+c] : 0.f; }
    for (int k = t; k < 24;  k += BT){
        sf[SF_BM+k] = (k<18)? bm[k] : 0.f;
        sf[SF_BU+k] = (k<18)? bu[k] : 0.f;
        sf[SF_BF+k] = (k<18)? bf[k] : 0.f;
    }
    if (t == 0) sf[SF_BR] = br[0];

    // ---- fp16 B matrices (padding zeros baked in) ----
    for (int idx = t; idx < 8*24; idx += BT){
        int k = idx/24, nn = idx%24;
        float v = (k < 6 && nn < 18) ? Wf[k*18 + nn] : 0.f;
        ((__half*)(smc + WFB_OFF))[idx] = __float2half(v);
    }
    for (int idx = t; idx < 32*24; idx += BT){
        int k = idx/24, nn = idx%24;
        float v1=0.f, v2=0.f, vh=0.f, vm=0.f;
        if (k < 18 && nn < 18){
            v1 = Wm[k*18 + nn];                               // h_i part
            v2 = Wm[(18+k)*18 + nn];                          // h_{i+1} part
            vh = Wu[(18+k)*18 + nn] + Wu[(36+k)*18 + nn];     // folded (U==h)
            vm = Wu[k*18 + nn];
        }
        ((__half*)(smc + WM1_OFF))[idx] = __float2half(v1);
        ((__half*)(smc + WM2_OFF))[idx] = __float2half(v2);
        ((__half*)(smc + WUH_OFF))[idx] = __float2half(vh);
        ((__half*)(smc + WUM_OFF))[idx] = __float2half(vm);
    }
    __syncthreads();

    // ---- x -> fp16 smem rows (k padded 6->8 per node, zeros baked) ----
    int e = blockIdx.x * BT + t;
    if (e >= n) e = n - 1;                    // clamp; no early return (warp-collective mma)
    {
        float xv[30];
        const float2* xb = (const float2*)(x + (long long)e * 30);
        #pragma unroll
        for (int k = 0; k < 15; k++){ float2 v = xb[k]; xv[2*k]=v.x; xv[2*k+1]=v.y; }
        char* row = smc + X_OFF + t*XROWB;
        #pragma unroll
        for (int i = 0; i < 5; i++){
            u32 p0 = pkh2(xv[i*6+0], xv[i*6+1]);
            u32 p1 = pkh2(xv[i*6+2], xv[i*6+3]);
            u32 p2 = pkh2(xv[i*6+4], xv[i*6+5]);
            *(uint4*)(row + i*16) = make_uint4(p0, p1, p2, 0u);
        }
    }
    __syncwarp();

    // ================= MMA phase: warp = 2 tiles of 16 elements =================
    const int lane = t & 31;
    const int w    = t >> 5;

    u32 Bfb[3];
    u32 Bm1a[3][2], Bm2a[3][2], Bha[3][2], Bua[3][2];
    u32 Bm1b[3],    Bm2b[3],    Bhb[3],    Bub[3];
    {
        const __half* WF16 = (const __half*)(smc + WFB_OFF);
        const __half* W1 = (const __half*)(smc + WM1_OFF);
        const __half* W2 = (const __half*)(smc + WM2_OFF);
        const __half* WH = (const __half*)(smc + WUH_OFF);
        const __half* WM = (const __half*)(smc + WUM_OFF);
        #pragma unroll
        for (int nf = 0; nf < 3; nf++){
            Bfb[nf] = ldbfrag8(WF16, 0, nf, lane);
            ldbfrag16(W1, nf, lane, Bm1a[nf]);  Bm1b[nf] = ldbfrag8(W1, 16, nf, lane);
            ldbfrag16(W2, nf, lane, Bm2a[nf]);  Bm2b[nf] = ldbfrag8(W2, 16, nf, lane);
            ldbfrag16(WH, nf, lane, Bha[nf]);   Bhb[nf]  = ldbfrag8(WH, 16, nf, lane);
            ldbfrag16(WM, nf, lane, Bua[nf]);   Bub[nf]  = ldbfrag8(WM, 16, nf, lane);
        }
    }
    float bfv[3][2], bmv[3][2], buv[3][2];
    #pragma unroll
    for (int nf = 0; nf < 3; nf++){
        int c = nf*8 + (lane & 3)*2;
        bfv[nf][0] = sf[SF_BF + c]; bfv[nf][1] = sf[SF_BF + c + 1];
        bmv[nf][0] = sf[SF_BM + c]; bmv[nf][1] = sf[SF_BM + c + 1];
        buv[nf][0] = sf[SF_BU + c]; buv[nf][1] = sf[SF_BU + c + 1];
    }
    const float brv = sf[SF_BR];

    const u32 smem_base = (u32)__cvta_generic_to_shared(smc);
    const int lrow = lane & 15;

    #pragma unroll
    for (int tl = 0; tl < 2; tl++){
        const int rowbase = w*32 + tl*16;
        u32 xb2 = smem_base + X_OFF + (rowbase + lrow)*XROWB;

        // ---- layer1 on tensor cores: h_i = tanh(x_i@Wf + bf) -> hf fragments ----
        u32 hf[5][6];
        #pragma unroll
        for (int i = 0; i < 5; i++){
            u32 xf[2];
            ldm2(xb2 + i*16, xf);
            float d[3][4];
            #pragma unroll
            for (int nf = 0; nf < 3; nf++){
                d[nf][0]=bfv[nf][0]; d[nf][1]=bfv[nf][1];
                d[nf][2]=bfv[nf][0]; d[nf][3]=bfv[nf][1];
                mmas8(d[nf], xf, Bfb[nf]);
            }
            hf[i][0] = pkh2(tanhap(d[0][0]), tanhap(d[0][1]));
            hf[i][1] = pkh2(tanhap(d[0][2]), tanhap(d[0][3]));
            hf[i][2] = pkh2(tanhap(d[1][0]), tanhap(d[1][1]));
            hf[i][3] = pkh2(tanhap(d[1][2]), tanhap(d[1][3]));
            hf[i][4] = pkh2(tanhap(d[2][0]), tanhap(d[2][1]));
            hf[i][5] = pkh2(tanhap(d[2][2]), tanhap(d[2][3]));
        }

        // M_i = tanh(h_i@Wm1 + h_{i+1}@Wm2 + bm), split accumulators (2-deep chains)
        auto computeM = [&](int i, u32 Mf[6]){
            const int ip = (i + 1) % 5;
            float d[3][4], d2[3][4];
            #pragma unroll
            for (int nf = 0; nf < 3; nf++){
                d[nf][0]=bmv[nf][0]; d[nf][1]=bmv[nf][1];
                d[nf][2]=bmv[nf][0]; d[nf][3]=bmv[nf][1];
                d2[nf][0]=0.f; d2[nf][1]=0.f; d2[nf][2]=0.f; d2[nf][3]=0.f;
                mmas (d[nf],  &hf[i][0],  Bm1a[nf]);
                mmas (d2[nf], &hf[ip][0], Bm2a[nf]);
                mmas8(d[nf],  &hf[i][4],  Bm1b[nf]);
                mmas8(d2[nf], &hf[ip][4], Bm2b[nf]);
            }
            Mf[0] = pkh2(tanhap(d[0][0]+d2[0][0]), tanhap(d[0][1]+d2[0][1]));
            Mf[1] = pkh2(tanhap(d[0][2]+d2[0][2]), tanhap(d[0][3]+d2[0][3]));
            Mf[2] = pkh2(tanhap(d[1][0]+d2[1][0]), tanhap(d[1][1]+d2[1][1]));
            Mf[3] = pkh2(tanhap(d[1][2]+d2[1][2]), tanhap(d[1][3]+d2[1][3]));
            Mf[4] = pkh2(tanhap(d[2][0]+d2[2][0]), tanhap(d[2][1]+d2[2][1]));
            Mf[5] = pkh2(tanhap(d[2][2]+d2[2][2]), tanhap(d[2][3]+d2[2][3]));
        };

        u32 Mf[6];
        computeM(4, Mf);                      // M_4 (consumed by U_0)

        float pr = 0.f, pr8 = 0.f;
        #pragma unroll
        for (int i = 0; i < 5; i++){
            // ---- U_i = tanh(M_{i-1}@WuM + h_i@WuH + bu), split accumulators ----
            float d[3][4], d2[3][4];
            #pragma unroll
            for (int nf = 0; nf < 3; nf++){
                d[nf][0]=buv[nf][0]; d[nf][1]=buv[nf][1];
                d[nf][2]=buv[nf][0]; d[nf][3]=buv[nf][1];
                d2[nf][0]=0.f; d2[nf][1]=0.f; d2[nf][2]=0.f; d2[nf][3]=0.f;
                mmas (d[nf],  &hf[i][0], Bha[nf]);   // independent of Mf -> issues early
                mmas8(d[nf],  &hf[i][4], Bhb[nf]);
                mmas (d2[nf], &Mf[0],    Bua[nf]);
                mmas8(d2[nf], &Mf[4],    Bub[nf]);
            }
            #pragma unroll
            for (int nf = 0; nf < 3; nf++){
                int c = nf*8 + (lane & 3)*2;
                float w0 = sf[SF_WR + i*24 + c];
                float w1 = sf[SF_WR + i*24 + c + 1];
                pr  += tanhap(d[nf][0]+d2[nf][0])*w0 + tanhap(d[nf][1]+d2[nf][1])*w1;
                pr8 += tanhap(d[nf][2]+d2[nf][2])*w0 + tanhap(d[nf][3]+d2[nf][3])*w1;
            }
            if (i < 4) computeM(i, Mf);       // M_i feeds U_{i+1}
        }

        pr  += __shfl_xor_sync(0xffffffffu, pr, 1);
        pr  += __shfl_xor_sync(0xffffffffu, pr, 2);
        pr8 += __shfl_xor_sync(0xffffffffu, pr8, 1);
        pr8 += __shfl_xor_sync(0xffffffffu, pr8, 2);
        if ((lane & 3) == 0){
            int e0 = blockIdx.x * BT + rowbase + (lane >> 2);
            if (e0 < n)     out[e0]     = pr  + brv;
            if (e0 + 8 < n) out[e0 + 8] = pr8 + brv;
        }
    }
}

extern "C" void kernel_launch(void* const* d_in, const int* in_sizes, int n_in,
                              void* d_out, int out_size)
{
    const float* x  = (const float*)d_in[0];
    const float* Wf = (const float*)d_in[1];
    const float* bf = (const float*)d_in[2];
    const float* Wm = (const float*)d_in[3];
    const float* bm = (const float*)d_in[4];
    const float* Wu = (const float*)d_in[5];
    const float* bu = (const float*)d_in[6];
    const float* Wr = (const float*)d_in[7];
    const float* br = (const float*)d_in[8];
    float* out = (float*)d_out;

    cudaFuncSetAttribute(mp_kernel, cudaFuncAttributeMaxDynamicSharedMemorySize,
                         SMEM_BYTES);

    const int n = in_sizes[0] / 30;     // B  (x is [B,5,6])
    const int blocks = (n + BT - 1) / BT;
    mp_kernel<<<blocks, BT, SMEM_BYTES>>>(x, Wf, bf, Wm, bm, Wu, bu, Wr, br, out, n);
}

// round 16
// speedup vs baseline: 1.0455x; 1.0455x over previous
#include <cuda_runtime.h>
#include <cuda_fp16.h>

typedef unsigned int u32;
typedef unsigned long long u64;

#define BT 128
#define ROWB 240                 // h-only rows; 240B stride -> conflict-free ldmatrix
// fp32 scalar region (float indices)
#define SF_WF 0                  // 6 x 20
#define SF_BF 120                // 20
#define SF_WR 140                // 5 x 24 (zero-padded)
#define SF_BM 260                // 24
#define SF_BU 284                // 24
#define SF_BR 308
// fp16 B matrices, byte offsets ([32][24] each, rows 18-31 zero)
#define WM1_OFF 1248
#define WM2_OFF (WM1_OFF + 1536)
#define WUH_OFF (WM2_OFF + 1536)
#define WUM_OFF (WUH_OFF + 1536)
#define ACT_OFF (WUM_OFF + 1536)          // 7392 (16B aligned)
#define SMEM_BYTES (ACT_OFF + BT*ROWB)    // 38112 -> 4 CTAs/SM (reg-capped 128)

static __device__ __forceinline__ u64 dup2(float v){
    u64 r; asm("mov.b64 %0, {%1,%1};" : "=l"(r) : "f"(v)); return r;
}
static __device__ __forceinline__ void upk2(u64 v, float& lo, float& hi){
    asm("mov.b64 {%0,%1}, %2;" : "=f"(lo), "=f"(hi) : "l"(v));
}
static __device__ __forceinline__ u64 fma2(u64 a, u64 b, u64 c){
    u64 d; asm("fma.rn.f32x2 %0, %1, %2, %3;" : "=l"(d) : "l"(a), "l"(b), "l"(c));
    return d;
}
static __device__ __forceinline__ float tanhap(float x){
    float r; asm("tanh.approx.f32 %0, %1;" : "=f"(r) : "f"(x)); return r;
}
static __device__ __forceinline__ u32 pkh2(float a, float b){
    __half2 h = __floats2half2_rn(a, b);
    return *(u32*)&h;
}
// packed fp16x2 tanh: 1 MUFU op for 2 values (result feeds fp16 MMA anyway)
static __device__ __forceinline__ u32 tanh16x2(u32 p){
    u32 r; asm("tanh.approx.f16x2 %0, %1;" : "=r"(r) : "r"(p)); return r;
}
static __device__ __forceinline__ u32 tanh16p(float a, float b){
    return tanh16x2(pkh2(a, b));
}
// pairs 0..3 (floats 0..7)
static __device__ __forceinline__ void ldrowA(const float* s, int off, u64 w[4]){
    ulonglong2 q0 = *(const ulonglong2*)(s + off);
    ulonglong2 q1 = *(const ulonglong2*)(s + off + 4);
    w[0]=q0.x; w[1]=q0.y; w[2]=q1.x; w[3]=q1.y;
}
// pairs 4..8 (floats 8..17)
static __device__ __forceinline__ void ldrowB(const float* s, int off, u64 w[5]){
    ulonglong2 q0 = *(const ulonglong2*)(s + off + 8);
    ulonglong2 q1 = *(const ulonglong2*)(s + off + 12);
    w[0]=q0.x; w[1]=q0.y; w[2]=q1.x; w[3]=q1.y;
    w[4] = *(const u64*)(s + off + 16);
}
static __device__ __forceinline__ void ldm4(u32 addr, u32 a[4]){
    asm volatile("ldmatrix.sync.aligned.m8n8.x4.shared.b16 {%0,%1,%2,%3}, [%4];"
        : "=r"(a[0]),"=r"(a[1]),"=r"(a[2]),"=r"(a[3]) : "r"(addr));
}
static __device__ __forceinline__ void ldm2(u32 addr, u32 a[2]){
    asm volatile("ldmatrix.sync.aligned.m8n8.x2.shared.b16 {%0,%1}, [%2];"
        : "=r"(a[0]),"=r"(a[1]) : "r"(addr));
}
static __device__ __forceinline__ void mmas(float d[4], const u32 a[4], const u32 b[2]){
    asm volatile("mma.sync.aligned.m16n8k16.row.col.f32.f16.f16.f32 "
        "{%0,%1,%2,%3}, {%4,%5,%6,%7}, {%8,%9}, {%0,%1,%2,%3};"
        : "+f"(d[0]),"+f"(d[1]),"+f"(d[2]),"+f"(d[3])
        : "r"(a[0]),"r"(a[1]),"r"(a[2]),"r"(a[3]), "r"(b[0]),"r"(b[1]));
}
static __device__ __forceinline__ void mmas8(float d[4], const u32 a[2], u32 b){
    asm volatile("mma.sync.aligned.m16n8k8.row.col.f32.f16.f16.f32 "
        "{%0,%1,%2,%3}, {%4,%5}, {%6}, {%0,%1,%2,%3};"
        : "+f"(d[0]),"+f"(d[1]),"+f"(d[2]),"+f"(d[3])
        : "r"(a[0]),"r"(a[1]), "r"(b));
}
// k16 B fragment (.col): reg0={B[k0][n],B[k0+1][n]}, reg1={B[k0+8][n],B[k0+9][n]}
static __device__ __forceinline__ void ldbfrag16(const __half* W, int nf, int lane, u32 r[2]){
    int k0 = (lane & 3)*2;
    int nn = nf*8 + (lane >> 2);
    u32 a = __half_as_ushort(W[k0*24 + nn]);
    u32 b = __half_as_ushort(W[(k0+1)*24 + nn]);
    u32 c = __half_as_ushort(W[(k0+8)*24 + nn]);
    u32 d = __half_as_ushort(W[(k0+9)*24 + nn]);
    r[0] = a | (b << 16);
    r[1] = c | (d << 16);
}
// k8 B fragment over global k rows 16-23
static __device__ __forceinline__ u32 ldbfrag8(const __half* W, int nf, int lane){
    int k0 = 16 + (lane & 3)*2;
    int nn = nf*8 + (lane >> 2);
    return (u32)__half_as_ushort(W[k0*24 + nn])
         | ((u32)__half_as_ushort(W[(k0+1)*24 + nn]) << 16);
}

__global__ void __launch_bounds__(BT, 4) mp_kernel(
    const float* __restrict__ x,
    const float* __restrict__ Wf, const float* __restrict__ bf,
    const float* __restrict__ Wm, const float* __restrict__ bm,
    const float* __restrict__ Wu, const float* __restrict__ bu,
    const float* __restrict__ Wr, const float* __restrict__ br,
    float* __restrict__ out, int n)
{
    extern __shared__ __align__(16) char smc[];
    float* sf = (float*)smc;
    const int t = threadIdx.x;

    // ---- zero activation region (pads must be finite-zero for mma) ----
    for (int i = t; i < (BT*ROWB)/16; i += BT)
        *(uint4*)(smc + ACT_OFF + i*16) = make_uint4(0,0,0,0);

    // ---- fp32 scalars ----
    for (int k = t; k < 120; k += BT){ int r=k/20, c=k%20; sf[SF_WF+k] = (c<18)? Wf[r*18+c] : 0.f; }
    for (int k = t; k < 20;  k += BT) sf[SF_BF+k] = (k<18)? bf[k] : 0.f;
    for (int k = t; k < 120; k += BT){ int r=k/24, c=k%24; sf[SF_WR+k] = (c<18)? Wr[r*18+c] : 0.f; }
    for (int k = t; k < 24;  k += BT){ sf[SF_BM+k] = (k<18)? bm[k] : 0.f;
                                       sf[SF_BU+k] = (k<18)? bu[k] : 0.f; }
    if (t == 0) sf[SF_BR] = br[0];

    // ---- fp16 B matrices [32][24], rows 18-31 zero ----
    for (int idx = t; idx < 32*24; idx += BT){
        int k = idx/24, nn = idx%24;
        float v1=0.f, v2=0.f, vh=0.f, vm=0.f;
        if (k < 18 && nn < 18){
            v1 = Wm[k*18 + nn];                               // h_i part
            v2 = Wm[(18+k)*18 + nn];                          // h_{i+1} part
            vh = Wu[(18+k)*18 + nn] + Wu[(36+k)*18 + nn];     // folded (U==h)
            vm = Wu[k*18 + nn];
        }
        ((__half*)(smc + WM1_OFF))[idx] = __float2half(v1);
        ((__half*)(smc + WM2_OFF))[idx] = __float2half(v2);
        ((__half*)(smc + WUH_OFF))[idx] = __float2half(vh);
        ((__half*)(smc + WUM_OFF))[idx] = __float2half(vm);
    }
    __syncthreads();

    // ================= layer 1: SIMT fp32, thread = element, 2 channel passes =================
    int e = blockIdx.x * BT + t;
    if (e >= n) e = n - 1;                    // clamp; no early return (warp-collective mma)
    {
        float xv[30];
        const float2* xb = (const float2*)(x + (long long)e * 30);
        #pragma unroll
        for (int k = 0; k < 15; k++){ float2 v = xb[k]; xv[2*k]=v.x; xv[2*k+1]=v.y; }

        char* row = smc + ACT_OFF + t*ROWB;

        // ---- pass A: channels 0-7 ----
        {
            u64 acc[5][4];
            {
                u64 bb[4]; ldrowA(sf, SF_BF, bb);
                #pragma unroll
                for (int p = 0; p < 4; p++){
                    #pragma unroll
                    for (int i = 0; i < 5; i++) acc[i][p] = bb[p];
                }
            }
            #pragma unroll
            for (int f = 0; f < 6; f++){
                u64 w[4]; ldrowA(sf, SF_WF + f*20, w);
                #pragma unroll
                for (int i = 0; i < 5; i++){
                    u64 a = dup2(xv[i*6 + f]);
                    #pragma unroll
                    for (int p = 0; p < 4; p++) acc[i][p] = fma2(a, w[p], acc[i][p]);
                }
            }
            #pragma unroll
            for (int i = 0; i < 5; i++){
                u32 hp[4];
                #pragma unroll
                for (int p = 0; p < 4; p++){
                    float lo, hi; upk2(acc[i][p], lo, hi);
                    hp[p] = tanh16p(lo, hi);               // f16x2 tanh (1 MUFU / pair)
                }
                *(uint4*)(row + i*48) = make_uint4(hp[0],hp[1],hp[2],hp[3]);
            }
        }
        // ---- pass B: channels 8-17 ----
        {
            u64 acc[5][5];
            {
                u64 bb[5]; ldrowB(sf, SF_BF, bb);
                #pragma unroll
                for (int p = 0; p < 5; p++){
                    #pragma unroll
                    for (int i = 0; i < 5; i++) acc[i][p] = bb[p];
                }
            }
            #pragma unroll
            for (int f = 0; f < 6; f++){
                u64 w[5]; ldrowB(sf, SF_WF + f*20, w);
                #pragma unroll
                for (int i = 0; i < 5; i++){
                    u64 a = dup2(xv[i*6 + f]);
                    #pragma unroll
                    for (int p = 0; p < 5; p++) acc[i][p] = fma2(a, w[p], acc[i][p]);
                }
            }
            #pragma unroll
            for (int i = 0; i < 5; i++){
                u32 hp[5];
                #pragma unroll
                for (int p = 0; p < 5; p++){
                    float lo, hi; upk2(acc[i][p], lo, hi);
                    hp[p] = tanh16p(lo, hi);
                }
                *(uint4*)(row + i*48 + 16) = make_uint4(hp[0],hp[1],hp[2],hp[3]);
                *(u32*) (row + i*48 + 32)  = hp[4];
            }
        }
    }
    __syncwarp();

    // ================= MMA phase: warp = 2 tiles of 16 elements =================
    const int lane = t & 31;
    const int w    = t >> 5;

    // B fragments: k16 chunk (2 regs) + k8 chunk (1 reg) per n-frag
    u32 Bm1a[3][2], Bm2a[3][2], Bha[3][2], Bua[3][2];
    u32 Bm1b[3],    Bm2b[3],    Bhb[3],    Bub[3];
    {
        const __half* W1 = (const __half*)(smc + WM1_OFF);
        const __half* W2 = (const __half*)(smc + WM2_OFF);
        const __half* WH = (const __half*)(smc + WUH_OFF);
        const __half* WM = (const __half*)(smc + WUM_OFF);
        #pragma unroll
        for (int nf = 0; nf < 3; nf++){
            ldbfrag16(W1, nf, lane, Bm1a[nf]);  Bm1b[nf] = ldbfrag8(W1, nf, lane);
            ldbfrag16(W2, nf, lane, Bm2a[nf]);  Bm2b[nf] = ldbfrag8(W2, nf, lane);
            ldbfrag16(WH, nf, lane, Bha[nf]);   Bhb[nf]  = ldbfrag8(WH, nf, lane);
            ldbfrag16(WM, nf, lane, Bua[nf]);   Bub[nf]  = ldbfrag8(WM, nf, lane);
        }
    }
    float bmv[3][2], buv[3][2];
    #pragma unroll
    for (int nf = 0; nf < 3; nf++){
        int c = nf*8 + (lane & 3)*2;
        bmv[nf][0] = sf[SF_BM + c]; bmv[nf][1] = sf[SF_BM + c + 1];
        buv[nf][0] = sf[SF_BU + c]; buv[nf][1] = sf[SF_BU + c + 1];
    }
    const float brv = sf[SF_BR];

    const u32 smem_base = (u32)__cvta_generic_to_shared(smc);
    const int lrow = lane & 15;
    const int lcol = (lane >> 4) << 4;

    #pragma unroll
    for (int tl = 0; tl < 2; tl++){
        const int rowbase = w*32 + tl*16;
        u32 tb  = smem_base + ACT_OFF + rowbase*ROWB;
        u32 ab  = tb + lrow*ROWB + lcol;          // x4 base (cols 0-15)
        u32 ab2 = tb + lrow*ROWB + 32;            // x2 base (cols 16-23)

        // ---- load all 5 h fragments ONCE; ring runs register-only after this ----
        u32 hf[5][6];
        #pragma unroll
        for (int i = 0; i < 5; i++){
            ldm4(ab  + i*48, &hf[i][0]);
            ldm2(ab2 + i*48, &hf[i][4]);
        }

        // M_i = tanh(h_i@Wm1 + h_{i+1}@Wm2 + bm) packed straight into A-fragment regs
        auto computeM = [&](int i, u32 Mf[6]){
            const int ip = (i + 1) % 5;
            float d[3][4];
            #pragma unroll
            for (int nf = 0; nf < 3; nf++){
                d[nf][0]=bmv[nf][0]; d[nf][1]=bmv[nf][1];
                d[nf][2]=bmv[nf][0]; d[nf][3]=bmv[nf][1];
                mmas (d[nf], &hf[i][0],  Bm1a[nf]);
                mmas8(d[nf], &hf[i][4],  Bm1b[nf]);
                mmas (d[nf], &hf[ip][0], Bm2a[nf]);
                mmas8(d[nf], &hf[ip][4], Bm2b[nf]);
            }
            Mf[0] = tanh16p(d[0][0], d[0][1]);    // f16x2 tanh (1 MUFU / pair)
            Mf[1] = tanh16p(d[0][2], d[0][3]);
            Mf[2] = tanh16p(d[1][0], d[1][1]);
            Mf[3] = tanh16p(d[1][2], d[1][3]);
            Mf[4] = tanh16p(d[2][0], d[2][1]);
            Mf[5] = tanh16p(d[2][2], d[2][3]);
        };

        u32 Mf[6];
        computeM(4, Mf);                      // M_4 (consumed by U_0)

        float pr = 0.f, pr8 = 0.f;
        #pragma unroll
        for (int i = 0; i < 5; i++){
            // ---- U_i = tanh(M_{i-1}@WuM + h_i@WuH + bu) ----
            float d[3][4];
            #pragma unroll
            for (int nf = 0; nf < 3; nf++){
                d[nf][0]=buv[nf][0]; d[nf][1]=buv[nf][1];
                d[nf][2]=buv[nf][0]; d[nf][3]=buv[nf][1];
                mmas (d[nf], &hf[i][0], Bha[nf]);
                mmas8(d[nf], &hf[i][4], Bhb[nf]);
                mmas (d[nf], &Mf[0],    Bua[nf]);
                mmas8(d[nf], &Mf[4],    Bub[nf]);
            }
            #pragma unroll
            for (int nf = 0; nf < 3; nf++){
                int c = nf*8 + (lane & 3)*2;
                float w0 = sf[SF_WR + i*24 + c];
                float w1 = sf[SF_WR + i*24 + c + 1];
                pr  += tanhap(d[nf][0])*w0 + tanhap(d[nf][1])*w1;   // readout stays f32
                pr8 += tanhap(d[nf][2])*w0 + tanhap(d[nf][3])*w1;
            }
            if (i < 4) computeM(i, Mf);       // M_i feeds U_{i+1}
        }

        pr  += __shfl_xor_sync(0xffffffffu, pr, 1);
        pr  += __shfl_xor_sync(0xffffffffu, pr, 2);
        pr8 += __shfl_xor_sync(0xffffffffu, pr8, 1);
        pr8 += __shfl_xor_sync(0xffffffffu, pr8, 2);
        if ((lane & 3) == 0){
            int e0 = blockIdx.x * BT + rowbase + (lane >> 2);
            if (e0 < n)     out[e0]     = pr  + brv;
            if (e0 + 8 < n) out[e0 + 8] = pr8 + brv;
        }
    }
}

extern "C" void kernel_launch(void* const* d_in, const int* in_sizes, int n_in,
                              void* d_out, int out_size)
{
    const float* x  = (const float*)d_in[0];
    const float* Wf = (const float*)d_in[1];
    const float* bf = (const float*)d_in[2];
    const float* Wm = (const float*)d_in[3];
    const float* bm = (const float*)d_in[4];
    const float* Wu = (const float*)d_in[5];
    const float* bu = (const float*)d_in[6];
    const float* Wr = (const float*)d_in[7];
    const float* br = (const float*)d_in[8];
    float* out = (float*)d_out;

    cudaFuncSetAttribute(mp_kernel, cudaFuncAttributeMaxDynamicSharedMemorySize,
                         SMEM_BYTES);

    const int n = in_sizes[0] / 30;     // B  (x is [B,5,6])
    const int blocks = (n + BT - 1) / BT;
    mp_kernel<<<blocks, BT, SMEM_BYTES>>>(x, Wf, bf, Wm, bm, Wu, bu, Wr, br, out, n);
}